// round 15
// baseline (speedup 1.0000x reference)
#include <cuda_runtime.h>
#include <cuda_bf16.h>
#include <math.h>
#include <stdint.h>

#define BB 64
#define NNODE 500
#define DIMS 40
#define BN_SCALE 0.99999500003749968750f  // 1/sqrt(1+1e-5)

// ---------------- scratch (device globals; no allocation allowed) ----------------
__device__ uint32_t g_adp_bf [BB * 512 * 256];   // bf16x2 pairs, [b][row<512][256 kpairs]
__device__ uint32_t g_adp2_bf[BB * 512 * 256];
__device__ float g_M1[BB * NNODE * DIMS];
__device__ float g_M2[BB * NNODE * DIMS];
__device__ float g_S0 [BB * NNODE * 512];
__device__ float g_S1 [BB * NNODE * 512];
__device__ __nv_bfloat16 g_G  [BB * NNODE * 512];
__device__ __nv_bfloat16 g_Y1 [BB * NNODE * 512];
__device__ __nv_bfloat16 g_Y2 [BB * NNODE * 512];
__device__ __nv_bfloat16 g_G01[BB * NNODE * 512];
__device__ __nv_bfloat16 g_Z1 [BB * NNODE * 256];
__device__ __nv_bfloat16 g_Z2 [BB * NNODE * 256];
__device__ float g_SK [BB * NNODE * 304];

__device__ __forceinline__ uint32_t pk2(float lo, float hi) {
    uint32_t u;
    asm("cvt.rn.bf16x2.f32 %0, %1, %2;" : "=r"(u) : "f"(hi), "f"(lo));
    return u;
}

// ---------------- fused T+M per batch:  M[b] = p2 @ (p1[ind[b]] . pk) ----------------
__global__ __launch_bounds__(512) void k_TM(
        const float* __restrict__ p1, const float* __restrict__ pk,
        const int* __restrict__ ind, const float* __restrict__ p2,
        float* __restrict__ Mout) {
    int b = blockIdx.x;
    __shared__ float te[DIMS];
    __shared__ float Ts[DIMS][DIMS];
    int tid = threadIdx.x;
    if (tid < DIMS) te[tid] = p1[ind[b] * DIMS + tid];
    __syncthreads();
    for (int i = tid; i < DIMS * DIMS; i += 512) {
        float s = 0.f;
#pragma unroll
        for (int ii = 0; ii < DIMS; ii++) s += te[ii] * pk[ii * DIMS * DIMS + i];
        Ts[i / DIMS][i % DIMS] = s;
    }
    __syncthreads();
    if (tid < NNODE) {
        float p2r[DIMS];
        const float* p2w = p2 + tid * DIMS;
#pragma unroll
        for (int j = 0; j < DIMS; j++) p2r[j] = __ldg(p2w + j);
        float* Mo = Mout + ((size_t)b * NNODE + tid) * DIMS;
#pragma unroll 4
        for (int k = 0; k < DIMS; k++) {
            float s = 0.f;
#pragma unroll
            for (int j = 0; j < DIMS; j++) s += p2r[j] * Ts[j][k];
            Mo[k] = s;
        }
    }
}

// ---------------- adjacency: E = M_tile @ p3^T, relu, softmax, bf16 pack ----------
#define RT 16
#define CT 50
__global__ __launch_bounds__(256) void k_adpE(
        const float* __restrict__ M, const float* __restrict__ p3,
        uint32_t* __restrict__ Abf) {
    int b = blockIdx.y;
    int row0 = blockIdx.x * RT;
    __shared__ float Ms[RT][DIMS];
    __shared__ float p3s[CT][DIMS + 1];
    __shared__ float Et[RT][504];
    int tid = threadIdx.x;
    int ty = tid >> 5, tx = tid & 31;

    for (int i = tid; i < RT * DIMS; i += 256) {
        int rr = i / DIMS, kk = i % DIMS;
        int grow = row0 + rr;
        Ms[rr][kk] = (grow < NNODE) ? M[((size_t)b * NNODE + grow) * DIMS + kk] : 0.f;
    }
    for (int c0 = 0; c0 < NNODE; c0 += CT) {
        __syncthreads();
        for (int i = tid; i < CT * DIMS; i += 256) {
            int cc = i / DIMS, kk = i % DIMS;
            p3s[cc][kk] = p3[(c0 + cc) * DIMS + kk];
        }
        __syncthreads();
#pragma unroll
        for (int j = 0; j < 2; j++) {
            int cc = tx + 32 * j;
            if (cc < CT) {
                float a0 = 0.f, a1 = 0.f;
                int r0 = ty * 2;
#pragma unroll
                for (int k = 0; k < DIMS; k++) {
                    float pv = p3s[cc][k];
                    a0 += Ms[r0][k] * pv;
                    a1 += Ms[r0 + 1][k] * pv;
                }
                Et[r0][c0 + cc]     = fmaxf(a0, 0.f);
                Et[r0 + 1][c0 + cc] = fmaxf(a1, 0.f);
            }
        }
    }
    __syncthreads();
#pragma unroll
    for (int rr = ty * 2; rr < ty * 2 + 2; rr++) {
        int grow = row0 + rr;
        float m = 0.f;
        for (int jv = tx; jv < NNODE; jv += 32) m = fmaxf(m, Et[rr][jv]);
#pragma unroll
        for (int off = 16; off > 0; off >>= 1) m = fmaxf(m, __shfl_xor_sync(0xffffffffu, m, off));
        float s = 0.f;
        for (int jv = tx; jv < NNODE; jv += 32) {
            float e = __expf(Et[rr][jv] - m);
            Et[rr][jv] = e; s += e;
        }
#pragma unroll
        for (int off = 16; off > 0; off >>= 1) s += __shfl_xor_sync(0xffffffffu, s, off);
        float inv = 1.f / s;
        if (grow < NNODE) {
            uint32_t* Arow = Abf + ((size_t)b * 512 + grow) * 256;
            for (int c = tx; c < 250; c += 32)
                Arow[c] = pk2(Et[rr][2 * c] * inv, Et[rr][2 * c + 1] * inv);
            if (tx < 6) Arow[250 + tx] = 0u;
        }
    }
}

// ---------------- layer-0: fused start + gated conv + skip ----------------
__global__ void k_gated0(const float* __restrict__ inp,
                         const float* __restrict__ sw, const float* __restrict__ sb,
                         float* __restrict__ S0, __nv_bfloat16* __restrict__ G,
                         const float* __restrict__ fw, const float* __restrict__ fb,
                         const float* __restrict__ gw, const float* __restrict__ gb,
                         const float* __restrict__ skw, const float* __restrict__ skb,
                         float* __restrict__ SK, int skoff) {
    const int d = 1, Tin = 16, Ti = 15, nthr = 32 * Ti;
    int bn = blockIdx.x;
    int b = bn / NNODE, n = bn % NNODE;
    __shared__ float xraw[32];
    __shared__ float sx[512];
    __shared__ float sG0[256];
    int tid = threadIdx.x;
    if (tid < 32) {
        int t = tid & 15, s2 = tid >> 4;
        xraw[s2 * 16 + t] = inp[(((size_t)b * 16 + t) * NNODE + n) * 2 + s2];
    }
    __syncthreads();
    for (int i = tid; i < 512; i += nthr) {
        int t = i & 15, sc = i >> 4;
        float v = xraw[(sc >> 4) * 16 + t] * __ldg(sw + sc) + __ldg(sb + sc);
        sx[i] = v;
        S0[(size_t)bn * 512 + i] = v;
    }
    __syncthreads();
    int s = tid / (16 * Ti);
    int r = tid % (16 * Ti);
    int o = r / Ti, t = r % Ti;
    float f = __ldg(fb + s * 16 + o), g = __ldg(gb + s * 16 + o);
    int base = s * 16 * Tin + t;
    const float* fwp = fw + (s * 16 + o) * 32;
    const float* gwp = gw + (s * 16 + o) * 32;
#pragma unroll
    for (int c = 0; c < 16; c++) {
        float xa = sx[base + c * Tin];
        float xb2 = sx[base + c * Tin + d];
        f += __ldg(fwp + 2 * c) * xa + __ldg(fwp + 2 * c + 1) * xb2;
        g += __ldg(gwp + 2 * c) * xa + __ldg(gwp + 2 * c + 1) * xb2;
    }
    float val = tanhf(f) * (1.f / (1.f + expf(-g)));
    G[(size_t)bn * nthr + tid] = __float2bfloat16(val);
    if (s == 0) sG0[r] = val;
    __syncthreads();
    if (tid < 8 * Ti) {
        int c = tid / Ti, tt = tid % Ti;
        float acc = __ldg(skb + c);
        const float* wp = skw + c * 16;
#pragma unroll
        for (int k = 0; k < 16; k++) acc += __ldg(wp + k) * sG0[k * Ti + tt];
        SK[(size_t)bn * 304 + skoff + tid] = acc;
    }
}

// ---------------- layers 1-3: gated conv + skip (S fp32 in, G bf16 out) ----------
__global__ void k_gated(const float* __restrict__ S, __nv_bfloat16* __restrict__ G,
                        const float* __restrict__ fw, const float* __restrict__ fb,
                        const float* __restrict__ gw, const float* __restrict__ gb,
                        const float* __restrict__ skw, const float* __restrict__ skb,
                        float* __restrict__ SK, int skoff,
                        int d, int Tin, int Ti) {
    int bn = blockIdx.x;
    int nthr = 32 * Ti;
    __shared__ float sx[512];
    __shared__ float sG0[256];
    int tid = threadIdx.x;
    int rowlen = 32 * Tin;
    for (int i = tid; i < rowlen; i += nthr) sx[i] = S[(size_t)bn * rowlen + i];
    __syncthreads();
    int s = tid / (16 * Ti);
    int r = tid % (16 * Ti);
    int o = r / Ti, t = r % Ti;
    float f = __ldg(fb + s * 16 + o), g = __ldg(gb + s * 16 + o);
    int base = s * 16 * Tin + t;
    const float* fwp = fw + (s * 16 + o) * 32;
    const float* gwp = gw + (s * 16 + o) * 32;
#pragma unroll
    for (int c = 0; c < 16; c++) {
        float xa = sx[base + c * Tin];
        float xb2 = sx[base + c * Tin + d];
        f += __ldg(fwp + 2 * c) * xa + __ldg(fwp + 2 * c + 1) * xb2;
        g += __ldg(gwp + 2 * c) * xa + __ldg(gwp + 2 * c + 1) * xb2;
    }
    float val = tanhf(f) * (1.f / (1.f + expf(-g)));
    if (G) G[(size_t)bn * nthr + tid] = __float2bfloat16(val);
    if (s == 0) sG0[r] = val;
    __syncthreads();
    if (tid < 8 * Ti) {
        int c = tid / Ti, tt = tid % Ti;
        float acc = __ldg(skb + c);
        const float* wp = skw + c * 16;
#pragma unroll
        for (int k = 0; k < 16; k++) acc += __ldg(wp + k) * sG0[k * Ti + tt];
        SK[(size_t)bn * 304 + skoff + tid] = acc;
    }
}

// ---------------- tensor-core batched graph GEMM (bf16 in/out, cp.async A) --------
__device__ __forceinline__ void mma_bf16(float* c, const uint32_t* a, const uint32_t* b) {
    asm volatile(
        "mma.sync.aligned.m16n8k16.row.col.f32.bf16.bf16.f32 "
        "{%0,%1,%2,%3}, {%4,%5,%6,%7}, {%8,%9}, {%0,%1,%2,%3};"
        : "+f"(c[0]), "+f"(c[1]), "+f"(c[2]), "+f"(c[3])
        : "r"(a[0]), "r"(a[1]), "r"(a[2]), "r"(a[3]), "r"(b[0]), "r"(b[1]));
}

#define GP 136
#define AP 20

__global__ __launch_bounds__(256, 2) void k_gemm_tc(
        const uint32_t* __restrict__ Abf, const __nv_bfloat16* __restrict__ Xb,
        __nv_bfloat16* __restrict__ Yb, int L,
        int xstride, int xoff, int ystride, int yoff) {
    int b = blockIdx.z;
    const uint32_t* A = Abf + (size_t)b * 512 * 256;
    const __nv_bfloat16* X = Xb + (size_t)b * NNODE * xstride + xoff;
    __nv_bfloat16* Y = Yb + (size_t)b * NNODE * ystride + yoff;
    int row0 = blockIdx.y * 128, col0 = blockIdx.x * 128;

    __shared__ uint32_t As2[2][128][AP];
    __shared__ uint32_t Bs[2][16][GP];

    int tid = threadIdx.x;
    int lane = tid & 31, wid = tid >> 5;
    int warpM = wid >> 1, warpN = wid & 1;
    int g = lane >> 2, r = lane & 3;

    int ar0 = tid >> 2, ac0 = (tid & 3) * 4;
    int bN = tid & 127, bKP = tid >> 7;
    int colIdx = col0 + bN;
    bool colOK = colIdx < L;

    uint32_t rbp[8];
    float acc[2][8][4];
#pragma unroll
    for (int mi = 0; mi < 2; mi++)
#pragma unroll
        for (int ni = 0; ni < 8; ni++)
#pragma unroll
            for (int q = 0; q < 4; q++) acc[mi][ni][q] = 0.f;

#define CP_A(K0, ST) do {                                                        \
    int kb = (K0) >> 1;                                                          \
    _Pragma("unroll")                                                            \
    for (int i = 0; i < 2; i++) {                                                \
        int m = ar0 + i * 64;                                                    \
        uint32_t dst = (uint32_t)__cvta_generic_to_shared(&As2[ST][m][ac0]);     \
        const uint32_t* src = A + (size_t)(row0 + m) * 256 + kb + ac0;           \
        asm volatile("cp.async.cg.shared.global [%0], [%1], 16;" :: "r"(dst), "l"(src)); \
    }                                                                            \
    asm volatile("cp.async.commit_group;"); } while (0)

#define LOAD_B(K0) do {                                                          \
    _Pragma("unroll")                                                            \
    for (int i = 0; i < 8; i++) {                                                \
        int gk = (K0) + 2 * (bKP + 2 * i);                                       \
        uint32_t lo = 0, hi = 0;                                                 \
        if (colOK) {                                                             \
            if (gk < NNODE)     lo = *(const uint16_t*)(X + (size_t)gk * xstride + colIdx); \
            if (gk + 1 < NNODE) hi = *(const uint16_t*)(X + (size_t)(gk + 1) * xstride + colIdx); \
        }                                                                        \
        rbp[i] = lo | (hi << 16);                                                \
    } } while (0)

#define STS_B(ST) do {                                                           \
    _Pragma("unroll")                                                            \
    for (int i = 0; i < 8; i++)                                                  \
        Bs[ST][bKP + 2 * i][bN] = rbp[i];                                        \
    } while (0)

    CP_A(0, 0);
    LOAD_B(0);

    for (int k0 = 0; k0 < NNODE; k0 += 32) {
        int st = (k0 >> 5) & 1;
        bool nxt = (k0 + 32) < NNODE;
        if (nxt) CP_A(k0 + 32, st ^ 1);
        STS_B(st);
        if (nxt) asm volatile("cp.async.wait_group 1;");
        else     asm volatile("cp.async.wait_group 0;");
        __syncthreads();
        if (nxt) LOAD_B(k0 + 32);
#pragma unroll
        for (int half = 0; half < 2; half++) {
            int kb2 = half * 8;
            uint32_t af[2][4], bf[8][2];
#pragma unroll
            for (int mi = 0; mi < 2; mi++) {
                int mb = warpM * 32 + mi * 16;
                af[mi][0] = As2[st][mb + g][kb2 + r];
                af[mi][1] = As2[st][mb + g + 8][kb2 + r];
                af[mi][2] = As2[st][mb + g][kb2 + r + 4];
                af[mi][3] = As2[st][mb + g + 8][kb2 + r + 4];
            }
#pragma unroll
            for (int ni = 0; ni < 8; ni++) {
                int nb = warpN * 64 + ni * 8;
                bf[ni][0] = Bs[st][kb2 + r][nb + g];
                bf[ni][1] = Bs[st][kb2 + r + 4][nb + g];
            }
#pragma unroll
            for (int mi = 0; mi < 2; mi++)
#pragma unroll
                for (int ni = 0; ni < 8; ni++)
                    mma_bf16(acc[mi][ni], af[mi], bf[ni]);
        }
        if (nxt) __syncthreads();   // WAR fence for As2[st^1]
    }

#pragma unroll
    for (int mi = 0; mi < 2; mi++) {
#pragma unroll
        for (int ni = 0; ni < 8; ni++) {
            int row = row0 + warpM * 32 + mi * 16 + g;
            int col = col0 + warpN * 64 + ni * 8 + 2 * r;
#pragma unroll
            for (int h = 0; h < 2; h++) {
                int rr = row + 8 * h;
                if (rr >= NNODE) continue;
                float a0 = acc[mi][ni][2 * h], a1 = acc[mi][ni][2 * h + 1];
                if (col + 1 < L) {
                    *(uint32_t*)(Y + (size_t)rr * ystride + col) = pk2(a0, a1);
                } else if (col < L) {
                    Y[(size_t)rr * ystride + col] = __float2bfloat16(a0);
                }
            }
        }
    }
}

// ---------------- gconv pointwise: g = W*[G, Y1, Y2] + b (bf16 io) ----------------
__global__ void k_g01(const __nv_bfloat16* __restrict__ G, const __nv_bfloat16* __restrict__ Y1,
                      const __nv_bfloat16* __restrict__ Y2, const float* __restrict__ gw,
                      const float* __restrict__ gb, __nv_bfloat16* __restrict__ G01, int Ti) {
    int bn = blockIdx.x;
    int nthr = 32 * Ti;
    __shared__ float sg[512], sy1[512], sy2[512];
    size_t base = (size_t)bn * nthr;
    int tid = threadIdx.x;
    sg[tid]  = __bfloat162float(G[base + tid]);
    sy1[tid] = __bfloat162float(Y1[base + tid]);
    sy2[tid] = __bfloat162float(Y2[base + tid]);
    __syncthreads();
    int s = tid / (16 * Ti);
    int r = tid % (16 * Ti);
    int o = r / Ti, t = r % Ti;
    float acc = __ldg(gb + s * 16 + o);
    const float* w = gw + (s * 16 + o) * 48;
    int cb = s * 16 * Ti + t;
#pragma unroll
    for (int c = 0; c < 16; c++)
        acc += __ldg(w + c) * sg[cb + c * Ti] + __ldg(w + 16 + c) * sy1[cb + c * Ti]
             + __ldg(w + 32 + c) * sy2[cb + c * Ti];
    G01[base + tid] = __float2bfloat16(acc);
}

// ---------------- residual/state update (bf16 in, fp32 S out) ----------------
__global__ void k_update(const float* __restrict__ Sin, const __nv_bfloat16* __restrict__ G01,
                         const __nv_bfloat16* __restrict__ Z1, const __nv_bfloat16* __restrict__ Z2,
                         const float* __restrict__ gaw, const float* __restrict__ gab,
                         float* __restrict__ Sout, int d, int Tin, int Ti) {
    int bn = blockIdx.x;
    int tid = threadIdx.x;
    int nthr = 32 * Ti;
    int rl = 16 * Ti;
    __shared__ float sg1[256], sz1[256], sz2[256];
    size_t gbase = (size_t)bn * nthr;
    for (int i = tid; i < rl; i += nthr) {
        sg1[i] = __bfloat162float(G01[gbase + rl + i]);
        sz1[i] = __bfloat162float(Z1[(size_t)bn * rl + i]);
        sz2[i] = __bfloat162float(Z2[(size_t)bn * rl + i]);
    }
    __syncthreads();
    int s = tid / rl;
    int r = tid % rl;
    int c = r / Ti, t = r % Ti;
    float out;
    if (s == 0) {
        float xap = __ldg(gab + c);
        const float* w = gaw + c * 48;
#pragma unroll
        for (int k = 0; k < 16; k++)
            xap += __ldg(w + k) * sg1[k * Ti + t] + __ldg(w + 16 + k) * sz1[k * Ti + t]
                 + __ldg(w + 32 + k) * sz2[k * Ti + t];
        float g0 = __bfloat162float(G01[gbase + c * Ti + t]);
        float r0 = Sin[(size_t)bn * (32 * Tin) + c * Tin + (t + d)];
        out = (2.f * g0 + xap + r0) * BN_SCALE;
    } else {
        out = Sin[(size_t)bn * (32 * Tin) + (16 + c) * Tin + (t + d)] * BN_SCALE;
    }
    Sout[gbase + tid] = out;
}

// ---------------- end convs ----------------
__global__ void k_end(const float* __restrict__ SK, const float* __restrict__ e1w,
                      const float* __restrict__ e1b, const float* __restrict__ e2w,
                      const float* __restrict__ e2b, float* __restrict__ out) {
    int warp = threadIdx.x >> 5, lane = threadIdx.x & 31;
    int bn = blockIdx.x * 4 + warp;
    if (bn >= BB * NNODE) return;
    int b = bn / NNODE, n = bn % NNODE;
    const float* sk = SK + (size_t)bn * 304;
    float acc[16];
#pragma unroll
    for (int o = 0; o < 16; o++) acc[o] = 0.f;
    for (int k = lane; k < 304; k += 32) {
        float v = fmaxf(sk[k], 0.f);
#pragma unroll
        for (int o = 0; o < 16; o++) acc[o] += __ldg(e1w + o * 304 + k) * v;
    }
#pragma unroll
    for (int o = 0; o < 16; o++) {
#pragma unroll
        for (int off = 16; off > 0; off >>= 1)
            acc[o] += __shfl_xor_sync(0xffffffff, acc[o], off);
    }
    if (lane == 0) {
        float e1[16];
#pragma unroll
        for (int o = 0; o < 16; o++) e1[o] = fmaxf(acc[o] + e1b[o], 0.f);
#pragma unroll
        for (int o2 = 0; o2 < 3; o2++) {
            float s = e2b[o2];
#pragma unroll
            for (int o = 0; o < 16; o++) s += e2w[o2 * 16 + o] * e1[o];
            out[((size_t)b * 3 + o2) * NNODE + n] = s;
        }
    }
}

// ---------------- host orchestration ----------------
extern "C" void kernel_launch(void* const* d_in, const int* in_sizes, int n_in,
                              void* d_out, int out_size) {
    const float* inputs  = (const float*)d_in[0];
    const int*   ind     = (const int*)  d_in[1];
    const float* start_w = (const float*)d_in[2];
    const float* start_b = (const float*)d_in[3];
    const float* p1      = (const float*)d_in[4];
    const float* p2      = (const float*)d_in[5];
    const float* p3      = (const float*)d_in[6];
    const float* pk      = (const float*)d_in[7];
    const float* a2p1    = (const float*)d_in[8];
    const float* a2p2    = (const float*)d_in[9];
    const float* a2p3    = (const float*)d_in[10];
    const float* a2pk    = (const float*)d_in[11];
    const float* filt_w  = (const float*)d_in[12];
    const float* filt_b  = (const float*)d_in[13];
    const float* gate_w  = (const float*)d_in[14];
    const float* gate_b  = (const float*)d_in[15];
    const float* gconv_w = (const float*)d_in[16];
    const float* gconv_b = (const float*)d_in[17];
    const float* ga_w    = (const float*)d_in[18];
    const float* ga_b    = (const float*)d_in[19];
    const float* skip_w  = (const float*)d_in[20];
    const float* skip_b  = (const float*)d_in[21];
    const float* end1_w  = (const float*)d_in[22];
    const float* end1_b  = (const float*)d_in[23];
    const float* end2_w  = (const float*)d_in[24];
    const float* end2_b  = (const float*)d_in[25];
    float* out = (float*)d_out;

    uint32_t *adp, *adp2;
    float *M1, *M2, *S0, *S1, *SK;
    __nv_bfloat16 *G, *Y1, *Y2, *G01, *Z1, *Z2;
    cudaGetSymbolAddress((void**)&adp,  g_adp_bf);
    cudaGetSymbolAddress((void**)&adp2, g_adp2_bf);
    cudaGetSymbolAddress((void**)&M1,   g_M1);
    cudaGetSymbolAddress((void**)&M2,   g_M2);
    cudaGetSymbolAddress((void**)&S0,   g_S0);
    cudaGetSymbolAddress((void**)&S1,   g_S1);
    cudaGetSymbolAddress((void**)&G,    g_G);
    cudaGetSymbolAddress((void**)&Y1,   g_Y1);
    cudaGetSymbolAddress((void**)&Y2,   g_Y2);
    cudaGetSymbolAddress((void**)&G01,  g_G01);
    cudaGetSymbolAddress((void**)&Z1,   g_Z1);
    cudaGetSymbolAddress((void**)&Z2,   g_Z2);
    cudaGetSymbolAddress((void**)&SK,   g_SK);

    const int dil[4]     = {1, 2, 4, 8};
    const int skipoff[4] = {184, 80, 8, 0};
    const int Tlen[5]    = {16, 15, 13, 9, 1};

    dim3 adpGrid(32, BB);
    k_TM<<<BB, 512>>>(p1, pk, ind, p2, M1);                              // 0
    k_TM<<<BB, 512>>>(a2p1, a2pk, ind, a2p2, M2);                        // 1
    k_gated0<<<BB * NNODE, 480>>>(inputs, start_w, start_b, S0, G,
        filt_w, filt_b, gate_w, gate_b, skip_w, skip_b, SK, skipoff[0]); // 2
    k_adpE<<<adpGrid, 256>>>(M1, p3, adp);                               // 3 <- profiled
    k_adpE<<<adpGrid, 256>>>(M2, a2p3, adp2);                            // 4

    float* Sbuf[2] = {S0, S1};
    for (int i = 0; i < 3; i++) {
        int Ti = Tlen[i + 1];              // T after layer i
        int L = 32 * Ti;
        dim3 grid((L + 127) / 128, (NNODE + 127) / 128, BB);
        k_gemm_tc<<<grid, 256>>>(adp, G,  Y1, L, L, 0, L, 0);
        k_gemm_tc<<<grid, 256>>>(adp, Y1, Y2, L, L, 0, L, 0);
        k_g01<<<BB * NNODE, L>>>(G, Y1, Y2,
            gconv_w + i * 1536, gconv_b + i * 32, G01, Ti);
        int L2 = 16 * Ti;
        dim3 grid2((L2 + 127) / 128, (NNODE + 127) / 128, BB);
        k_gemm_tc<<<grid2, 256>>>(adp2, G01, Z1, L2, L, L2, L2, 0);
        k_gemm_tc<<<grid2, 256>>>(adp2, Z1,  Z2, L2, L2, 0, L2, 0);
        k_update<<<BB * NNODE, L>>>(Sbuf[i & 1], G01, Z1, Z2,
            ga_w + i * 768, ga_b + i * 16, Sbuf[(i + 1) & 1], dil[i], Tlen[i], Ti);
        int j = i + 1;
        __nv_bfloat16* Gout = (j < 3) ? G : (__nv_bfloat16*)nullptr;  // layer-3 G dead
        k_gated<<<BB * NNODE, 32 * Tlen[j + 1]>>>(Sbuf[(i + 1) & 1], Gout,
            filt_w + j * 1024, filt_b + j * 32,
            gate_w + j * 1024, gate_b + j * 32,
            skip_w + j * 128, skip_b + j * 8, SK, skipoff[j],
            dil[j], Tlen[j], Tlen[j + 1]);
    }

    k_end<<<(BB * NNODE + 3) / 4, 128>>>(SK, end1_w, end1_b, end2_w, end2_b, out);
}

// round 16
// speedup vs baseline: 1.3583x; 1.3583x over previous
#include <cuda_runtime.h>
#include <math.h>
#include <stdint.h>

#define BB 64
#define NNODE 500
#define DIMS 40
#define BN_SCALE 0.99999500003749968750f  // 1/sqrt(1+1e-5)

// ---------------- scratch (device globals; no allocation allowed) ----------------
__device__ uint32_t g_adp_bf [BB * 512 * 256];   // bf16x2 pairs, [b][row<512][256 kpairs]
__device__ uint32_t g_adp2_bf[BB * 512 * 256];
__device__ float g_M1[BB * NNODE * DIMS];
__device__ float g_M2[BB * NNODE * DIMS];
__device__ float g_S0 [BB * NNODE * 512];
__device__ float g_S1 [BB * NNODE * 512];
__device__ float g_G  [BB * NNODE * 512];
__device__ float g_Y1 [BB * NNODE * 512];
__device__ float g_Y2 [BB * NNODE * 512];
__device__ float g_G01[BB * NNODE * 512];
__device__ float g_Z1 [BB * NNODE * 256];
__device__ float g_Z2 [BB * NNODE * 256];
__device__ float g_SK [BB * NNODE * 304];

__device__ __forceinline__ uint32_t pk2(float lo, float hi) {
    uint32_t u;
    asm("cvt.rn.bf16x2.f32 %0, %1, %2;" : "=r"(u) : "f"(hi), "f"(lo));
    return u;
}

// ---------------- fused T+M per batch:  M[b] = p2 @ (p1[ind[b]] . pk) ----------------
__global__ __launch_bounds__(512) void k_TM(
        const float* __restrict__ p1, const float* __restrict__ pk,
        const int* __restrict__ ind, const float* __restrict__ p2,
        float* __restrict__ Mout) {
    int b = blockIdx.x;
    __shared__ float te[DIMS];
    __shared__ float Ts[DIMS][DIMS];
    int tid = threadIdx.x;
    if (tid < DIMS) te[tid] = p1[ind[b] * DIMS + tid];
    __syncthreads();
    for (int i = tid; i < DIMS * DIMS; i += 512) {
        float s = 0.f;
#pragma unroll
        for (int ii = 0; ii < DIMS; ii++) s += te[ii] * pk[ii * DIMS * DIMS + i];
        Ts[i / DIMS][i % DIMS] = s;
    }
    __syncthreads();
    if (tid < NNODE) {
        float p2r[DIMS];
        const float* p2w = p2 + tid * DIMS;
#pragma unroll
        for (int j = 0; j < DIMS; j++) p2r[j] = __ldg(p2w + j);
        float* Mo = Mout + ((size_t)b * NNODE + tid) * DIMS;
#pragma unroll 4
        for (int k = 0; k < DIMS; k++) {
            float s = 0.f;
#pragma unroll
            for (int j = 0; j < DIMS; j++) s += p2r[j] * Ts[j][k];
            Mo[k] = s;
        }
    }
}

// ---------------- adjacency: E = M_tile @ p3^T, relu, softmax, bf16 pack ----------
#define RT 16
#define CT 50
__global__ __launch_bounds__(256) void k_adpE(
        const float* __restrict__ M, const float* __restrict__ p3,
        uint32_t* __restrict__ Abf) {
    int b = blockIdx.y;
    int row0 = blockIdx.x * RT;
    __shared__ float Ms[RT][DIMS];
    __shared__ float p3s[CT][DIMS + 1];
    __shared__ float Et[RT][504];
    int tid = threadIdx.x;
    int ty = tid >> 5, tx = tid & 31;

    for (int i = tid; i < RT * DIMS; i += 256) {
        int rr = i / DIMS, kk = i % DIMS;
        int grow = row0 + rr;
        Ms[rr][kk] = (grow < NNODE) ? M[((size_t)b * NNODE + grow) * DIMS + kk] : 0.f;
    }
    for (int c0 = 0; c0 < NNODE; c0 += CT) {
        __syncthreads();
        for (int i = tid; i < CT * DIMS; i += 256) {
            int cc = i / DIMS, kk = i % DIMS;
            p3s[cc][kk] = p3[(c0 + cc) * DIMS + kk];
        }
        __syncthreads();
        // 2 rows x 2 cols per thread: 4 LDS per 4 FMA (was 3 per 2)
        {
            int r0 = ty * 2;
            int cc1 = tx + 32;
            bool c1ok = cc1 < CT;
            int cc1s = c1ok ? cc1 : tx;
            float a00 = 0.f, a01 = 0.f, a10 = 0.f, a11 = 0.f;
#pragma unroll
            for (int k = 0; k < DIMS; k++) {
                float m0 = Ms[r0][k], m1 = Ms[r0 + 1][k];
                float pv0 = p3s[tx][k];
                float pv1 = p3s[cc1s][k];
                a00 += m0 * pv0; a10 += m1 * pv0;
                a01 += m0 * pv1; a11 += m1 * pv1;
            }
            Et[r0][c0 + tx]     = fmaxf(a00, 0.f);
            Et[r0 + 1][c0 + tx] = fmaxf(a10, 0.f);
            if (c1ok) {
                Et[r0][c0 + cc1]     = fmaxf(a01, 0.f);
                Et[r0 + 1][c0 + cc1] = fmaxf(a11, 0.f);
            }
        }
    }
    __syncthreads();
#pragma unroll
    for (int rr = ty * 2; rr < ty * 2 + 2; rr++) {
        int grow = row0 + rr;
        float m = 0.f;
        for (int jv = tx; jv < NNODE; jv += 32) m = fmaxf(m, Et[rr][jv]);
#pragma unroll
        for (int off = 16; off > 0; off >>= 1) m = fmaxf(m, __shfl_xor_sync(0xffffffffu, m, off));
        float s = 0.f;
        for (int jv = tx; jv < NNODE; jv += 32) {
            float e = __expf(Et[rr][jv] - m);
            Et[rr][jv] = e; s += e;
        }
#pragma unroll
        for (int off = 16; off > 0; off >>= 1) s += __shfl_xor_sync(0xffffffffu, s, off);
        float inv = 1.f / s;
        if (grow < NNODE) {
            uint32_t* Arow = Abf + ((size_t)b * 512 + grow) * 256;
            for (int c = tx; c < 250; c += 32)
                Arow[c] = pk2(Et[rr][2 * c] * inv, Et[rr][2 * c + 1] * inv);
            if (tx < 6) Arow[250 + tx] = 0u;
        }
    }
}

// ---------------- layer-0: fused start + gated conv + skip ----------------
__global__ void k_gated0(const float* __restrict__ inp,
                         const float* __restrict__ sw, const float* __restrict__ sb,
                         float* __restrict__ S0, float* __restrict__ G,
                         const float* __restrict__ fw, const float* __restrict__ fb,
                         const float* __restrict__ gw, const float* __restrict__ gb,
                         const float* __restrict__ skw, const float* __restrict__ skb,
                         float* __restrict__ SK, int skoff) {
    const int d = 1, Tin = 16, Ti = 15, nthr = 32 * Ti;
    int bn = blockIdx.x;
    int b = bn / NNODE, n = bn % NNODE;
    __shared__ float xraw[32];
    __shared__ float sx[512];
    __shared__ float sG0[256];
    int tid = threadIdx.x;
    if (tid < 32) {
        int t = tid & 15, s2 = tid >> 4;
        xraw[s2 * 16 + t] = inp[(((size_t)b * 16 + t) * NNODE + n) * 2 + s2];
    }
    __syncthreads();
    for (int i = tid; i < 512; i += nthr) {
        int t = i & 15, sc = i >> 4;
        float v = xraw[(sc >> 4) * 16 + t] * __ldg(sw + sc) + __ldg(sb + sc);
        sx[i] = v;
        S0[(size_t)bn * 512 + i] = v;
    }
    __syncthreads();
    int s = tid / (16 * Ti);
    int r = tid % (16 * Ti);
    int o = r / Ti, t = r % Ti;
    float f = __ldg(fb + s * 16 + o), g = __ldg(gb + s * 16 + o);
    int base = s * 16 * Tin + t;
    const float* fwp = fw + (s * 16 + o) * 32;
    const float* gwp = gw + (s * 16 + o) * 32;
#pragma unroll
    for (int c = 0; c < 16; c++) {
        float xa = sx[base + c * Tin];
        float xb2 = sx[base + c * Tin + d];
        f += __ldg(fwp + 2 * c) * xa + __ldg(fwp + 2 * c + 1) * xb2;
        g += __ldg(gwp + 2 * c) * xa + __ldg(gwp + 2 * c + 1) * xb2;
    }
    float val = tanhf(f) * (1.f / (1.f + expf(-g)));
    G[(size_t)bn * nthr + tid] = val;
    if (s == 0) sG0[r] = val;
    __syncthreads();
    if (tid < 8 * Ti) {
        int c = tid / Ti, tt = tid % Ti;
        float acc = __ldg(skb + c);
        const float* wp = skw + c * 16;
#pragma unroll
        for (int k = 0; k < 16; k++) acc += __ldg(wp + k) * sG0[k * Ti + tt];
        SK[(size_t)bn * 304 + skoff + tid] = acc;
    }
}

// ---------------- layers 1-3: gated conv + skip (dual-stream threads) -------------
// blockDim = 16*Ti; each thread computes both streams for its (o,t).
__global__ void k_gated(const float* __restrict__ S, float* __restrict__ G,
                        const float* __restrict__ fw, const float* __restrict__ fb,
                        const float* __restrict__ gw, const float* __restrict__ gb,
                        const float* __restrict__ skw, const float* __restrict__ skb,
                        float* __restrict__ SK, int skoff,
                        int d, int Tin, int Ti) {
    int bn = blockIdx.x;
    int nthr = 16 * Ti;
    __shared__ float sx[512];
    __shared__ float sG0[256];
    int tid = threadIdx.x;
    int rowlen = 32 * Tin;
    for (int i = tid; i < rowlen; i += nthr) sx[i] = S[(size_t)bn * rowlen + i];
    __syncthreads();
    int o = tid / Ti, t = tid % Ti;
    float vals0;
#pragma unroll
    for (int s = 0; s < 2; s++) {
        float f = __ldg(fb + s * 16 + o), g = __ldg(gb + s * 16 + o);
        int base = s * 16 * Tin + t;
        const float* fwp = fw + (s * 16 + o) * 32;
        const float* gwp = gw + (s * 16 + o) * 32;
#pragma unroll
        for (int c = 0; c < 16; c++) {
            float xa = sx[base + c * Tin];
            float xb2 = sx[base + c * Tin + d];
            f += __ldg(fwp + 2 * c) * xa + __ldg(fwp + 2 * c + 1) * xb2;
            g += __ldg(gwp + 2 * c) * xa + __ldg(gwp + 2 * c + 1) * xb2;
        }
        float val = tanhf(f) * (1.f / (1.f + expf(-g)));
        if (G) G[(size_t)bn * (32 * Ti) + s * 16 * Ti + o * Ti + t] = val;
        if (s == 0) vals0 = val;
    }
    sG0[o * Ti + t] = vals0;
    __syncthreads();
    if (tid < 8 * Ti) {
        int c = tid / Ti, tt = tid % Ti;
        float acc = __ldg(skb + c);
        const float* wp = skw + c * 16;
#pragma unroll
        for (int k = 0; k < 16; k++) acc += __ldg(wp + k) * sG0[k * Ti + tt];
        SK[(size_t)bn * 304 + skoff + tid] = acc;
    }
}

// ---------------- tensor-core batched graph GEMM (cp.async A, double-buffered) ----
__device__ __forceinline__ void mma_bf16(float* c, const uint32_t* a, const uint32_t* b) {
    asm volatile(
        "mma.sync.aligned.m16n8k16.row.col.f32.bf16.bf16.f32 "
        "{%0,%1,%2,%3}, {%4,%5,%6,%7}, {%8,%9}, {%0,%1,%2,%3};"
        : "+f"(c[0]), "+f"(c[1]), "+f"(c[2]), "+f"(c[3])
        : "r"(a[0]), "r"(a[1]), "r"(a[2]), "r"(a[3]), "r"(b[0]), "r"(b[1]));
}

#define GP 136
#define AP 20

__global__ __launch_bounds__(256, 2) void k_gemm_tc(
        const uint32_t* __restrict__ Abf, const float* __restrict__ Xb,
        float* __restrict__ Yb, int L,
        int xstride, int xoff, int ystride, int yoff) {
    int b = blockIdx.z;
    const uint32_t* A = Abf + (size_t)b * 512 * 256;
    const float* X = Xb + (size_t)b * NNODE * xstride + xoff;
    float* Y = Yb + (size_t)b * NNODE * ystride + yoff;
    int row0 = blockIdx.y * 128, col0 = blockIdx.x * 128;

    __shared__ uint32_t As2[2][128][AP];
    __shared__ uint32_t Bs[2][16][GP];

    int tid = threadIdx.x;
    int lane = tid & 31, wid = tid >> 5;
    int warpM = wid >> 1, warpN = wid & 1;
    int g = lane >> 2, r = lane & 3;

    int ar0 = tid >> 2, ac0 = (tid & 3) * 4;
    int bN = tid & 127, bKP = tid >> 7;
    bool colOK = (col0 + bN) < L;

    float rb[16];
    float acc[2][8][4];
#pragma unroll
    for (int mi = 0; mi < 2; mi++)
#pragma unroll
        for (int ni = 0; ni < 8; ni++)
#pragma unroll
            for (int q = 0; q < 4; q++) acc[mi][ni][q] = 0.f;

#define CP_A(K0, ST) do {                                                        \
    int kb = (K0) >> 1;                                                          \
    _Pragma("unroll")                                                            \
    for (int i = 0; i < 2; i++) {                                                \
        int m = ar0 + i * 64;                                                    \
        uint32_t dst = (uint32_t)__cvta_generic_to_shared(&As2[ST][m][ac0]);     \
        const uint32_t* src = A + (size_t)(row0 + m) * 256 + kb + ac0;           \
        asm volatile("cp.async.cg.shared.global [%0], [%1], 16;" :: "r"(dst), "l"(src)); \
    }                                                                            \
    asm volatile("cp.async.commit_group;"); } while (0)

#define LOAD_B(K0) do {                                                          \
    _Pragma("unroll")                                                            \
    for (int i = 0; i < 8; i++) {                                                \
        int gk = (K0) + 2 * (bKP + 2 * i);                                       \
        rb[2*i]   = (gk < NNODE && colOK)     ? X[(size_t)gk * xstride + col0 + bN] : 0.f; \
        rb[2*i+1] = (gk + 1 < NNODE && colOK) ? X[(size_t)(gk + 1) * xstride + col0 + bN] : 0.f; \
    } } while (0)

#define STS_B(ST) do {                                                           \
    _Pragma("unroll")                                                            \
    for (int i = 0; i < 8; i++)                                                  \
        Bs[ST][bKP + 2 * i][bN] = pk2(rb[2*i], rb[2*i+1]);                       \
    } while (0)

    CP_A(0, 0);
    LOAD_B(0);

    for (int k0 = 0; k0 < NNODE; k0 += 32) {
        int st = (k0 >> 5) & 1;
        bool nxt = (k0 + 32) < NNODE;
        if (nxt) CP_A(k0 + 32, st ^ 1);
        STS_B(st);
        if (nxt) asm volatile("cp.async.wait_group 1;");
        else     asm volatile("cp.async.wait_group 0;");
        __syncthreads();
        if (nxt) LOAD_B(k0 + 32);
#pragma unroll
        for (int half = 0; half < 2; half++) {
            int kb2 = half * 8;
            uint32_t af[2][4], bf[8][2];
#pragma unroll
            for (int mi = 0; mi < 2; mi++) {
                int mb = warpM * 32 + mi * 16;
                af[mi][0] = As2[st][mb + g][kb2 + r];
                af[mi][1] = As2[st][mb + g + 8][kb2 + r];
                af[mi][2] = As2[st][mb + g][kb2 + r + 4];
                af[mi][3] = As2[st][mb + g + 8][kb2 + r + 4];
            }
#pragma unroll
            for (int ni = 0; ni < 8; ni++) {
                int nb = warpN * 64 + ni * 8;
                bf[ni][0] = Bs[st][kb2 + r][nb + g];
                bf[ni][1] = Bs[st][kb2 + r + 4][nb + g];
            }
#pragma unroll
            for (int mi = 0; mi < 2; mi++)
#pragma unroll
                for (int ni = 0; ni < 8; ni++)
                    mma_bf16(acc[mi][ni], af[mi], bf[ni]);
        }
        if (nxt) __syncthreads();   // WAR fence for As2[st^1]
    }

#pragma unroll
    for (int mi = 0; mi < 2; mi++) {
#pragma unroll
        for (int ni = 0; ni < 8; ni++) {
            int row = row0 + warpM * 32 + mi * 16 + g;
            int col = col0 + warpN * 64 + ni * 8 + 2 * r;
            if (row < NNODE) {
                if (col < L)     Y[(size_t)row * ystride + col]     = acc[mi][ni][0];
                if (col + 1 < L) Y[(size_t)row * ystride + col + 1] = acc[mi][ni][1];
            }
            if (row + 8 < NNODE) {
                if (col < L)     Y[(size_t)(row + 8) * ystride + col]     = acc[mi][ni][2];
                if (col + 1 < L) Y[(size_t)(row + 8) * ystride + col + 1] = acc[mi][ni][3];
            }
        }
    }
}

// ---------------- gconv pointwise (dual-stream threads) ----------------
// blockDim = 16*Ti
__global__ void k_g01(const float* __restrict__ G, const float* __restrict__ Y1,
                      const float* __restrict__ Y2, const float* __restrict__ gw,
                      const float* __restrict__ gb, float* __restrict__ G01, int Ti) {
    int bn = blockIdx.x;
    int nthr = 16 * Ti;
    int full = 32 * Ti;
    __shared__ float sg[512], sy1[512], sy2[512];
    size_t base = (size_t)bn * full;
    int tid = threadIdx.x;
    for (int i = tid; i < full; i += nthr) {
        sg[i] = G[base + i]; sy1[i] = Y1[base + i]; sy2[i] = Y2[base + i];
    }
    __syncthreads();
    int o = tid / Ti, t = tid % Ti;
#pragma unroll
    for (int s = 0; s < 2; s++) {
        float acc = __ldg(gb + s * 16 + o);
        const float* w = gw + (s * 16 + o) * 48;
        int cb = s * 16 * Ti + t;
#pragma unroll
        for (int c = 0; c < 16; c++)
            acc += __ldg(w + c) * sg[cb + c * Ti] + __ldg(w + 16 + c) * sy1[cb + c * Ti]
                 + __ldg(w + 32 + c) * sy2[cb + c * Ti];
        G01[base + s * 16 * Ti + o * Ti + t] = acc;
    }
}

// ---------------- residual/state update (dual-stream threads) ----------------
// blockDim = 16*Ti
__global__ void k_update(const float* __restrict__ Sin, const float* __restrict__ G01,
                         const float* __restrict__ Z1, const float* __restrict__ Z2,
                         const float* __restrict__ gaw, const float* __restrict__ gab,
                         float* __restrict__ Sout, int d, int Tin, int Ti) {
    int bn = blockIdx.x;
    int tid = threadIdx.x;
    int rl = 16 * Ti;
    __shared__ float sg1[256], sz1[256], sz2[256];
    size_t gbase = (size_t)bn * (size_t)(32 * Ti);
    sg1[tid] = G01[gbase + rl + tid];
    sz1[tid] = Z1[(size_t)bn * rl + tid];
    sz2[tid] = Z2[(size_t)bn * rl + tid];
    __syncthreads();
    int c = tid / Ti, t = tid % Ti;
    // stream 0
    {
        float xap = __ldg(gab + c);
        const float* w = gaw + c * 48;
#pragma unroll
        for (int k = 0; k < 16; k++)
            xap += __ldg(w + k) * sg1[k * Ti + t] + __ldg(w + 16 + k) * sz1[k * Ti + t]
                 + __ldg(w + 32 + k) * sz2[k * Ti + t];
        float g0 = G01[gbase + c * Ti + t];
        float r0 = Sin[(size_t)bn * (32 * Tin) + c * Tin + (t + d)];
        Sout[gbase + c * Ti + t] = (2.f * g0 + xap + r0) * BN_SCALE;
    }
    // stream 1 (residual copy)
    Sout[gbase + rl + c * Ti + t] =
        Sin[(size_t)bn * (32 * Tin) + (16 + c) * Tin + (t + d)] * BN_SCALE;
}

// ---------------- end convs ----------------
__global__ void k_end(const float* __restrict__ SK, const float* __restrict__ e1w,
                      const float* __restrict__ e1b, const float* __restrict__ e2w,
                      const float* __restrict__ e2b, float* __restrict__ out) {
    int warp = threadIdx.x >> 5, lane = threadIdx.x & 31;
    int bn = blockIdx.x * 4 + warp;
    if (bn >= BB * NNODE) return;
    int b = bn / NNODE, n = bn % NNODE;
    const float* sk = SK + (size_t)bn * 304;
    float acc[16];
#pragma unroll
    for (int o = 0; o < 16; o++) acc[o] = 0.f;
    for (int k = lane; k < 304; k += 32) {
        float v = fmaxf(sk[k], 0.f);
#pragma unroll
        for (int o = 0; o < 16; o++) acc[o] += __ldg(e1w + o * 304 + k) * v;
    }
#pragma unroll
    for (int o = 0; o < 16; o++) {
#pragma unroll
        for (int off = 16; off > 0; off >>= 1)
            acc[o] += __shfl_xor_sync(0xffffffff, acc[o], off);
    }
    if (lane == 0) {
        float e1[16];
#pragma unroll
        for (int o = 0; o < 16; o++) e1[o] = fmaxf(acc[o] + e1b[o], 0.f);
#pragma unroll
        for (int o2 = 0; o2 < 3; o2++) {
            float s = e2b[o2];
#pragma unroll
            for (int o = 0; o < 16; o++) s += e2w[o2 * 16 + o] * e1[o];
            out[((size_t)b * 3 + o2) * NNODE + n] = s;
        }
    }
}

// ---------------- host orchestration ----------------
extern "C" void kernel_launch(void* const* d_in, const int* in_sizes, int n_in,
                              void* d_out, int out_size) {
    const float* inputs  = (const float*)d_in[0];
    const int*   ind     = (const int*)  d_in[1];
    const float* start_w = (const float*)d_in[2];
    const float* start_b = (const float*)d_in[3];
    const float* p1      = (const float*)d_in[4];
    const float* p2      = (const float*)d_in[5];
    const float* p3      = (const float*)d_in[6];
    const float* pk      = (const float*)d_in[7];
    const float* a2p1    = (const float*)d_in[8];
    const float* a2p2    = (const float*)d_in[9];
    const float* a2p3    = (const float*)d_in[10];
    const float* a2pk    = (const float*)d_in[11];
    const float* filt_w  = (const float*)d_in[12];
    const float* filt_b  = (const float*)d_in[13];
    const float* gate_w  = (const float*)d_in[14];
    const float* gate_b  = (const float*)d_in[15];
    const float* gconv_w = (const float*)d_in[16];
    const float* gconv_b = (const float*)d_in[17];
    const float* ga_w    = (const float*)d_in[18];
    const float* ga_b    = (const float*)d_in[19];
    const float* skip_w  = (const float*)d_in[20];
    const float* skip_b  = (const float*)d_in[21];
    const float* end1_w  = (const float*)d_in[22];
    const float* end1_b  = (const float*)d_in[23];
    const float* end2_w  = (const float*)d_in[24];
    const float* end2_b  = (const float*)d_in[25];
    float* out = (float*)d_out;

    uint32_t *adp, *adp2;
    float *M1, *M2, *S0, *S1, *G, *Y1, *Y2, *G01, *Z1, *Z2, *SK;
    cudaGetSymbolAddress((void**)&adp,  g_adp_bf);
    cudaGetSymbolAddress((void**)&adp2, g_adp2_bf);
    cudaGetSymbolAddress((void**)&M1,   g_M1);
    cudaGetSymbolAddress((void**)&M2,   g_M2);
    cudaGetSymbolAddress((void**)&S0,   g_S0);
    cudaGetSymbolAddress((void**)&S1,   g_S1);
    cudaGetSymbolAddress((void**)&G,    g_G);
    cudaGetSymbolAddress((void**)&Y1,   g_Y1);
    cudaGetSymbolAddress((void**)&Y2,   g_Y2);
    cudaGetSymbolAddress((void**)&G01,  g_G01);
    cudaGetSymbolAddress((void**)&Z1,   g_Z1);
    cudaGetSymbolAddress((void**)&Z2,   g_Z2);
    cudaGetSymbolAddress((void**)&SK,   g_SK);

    const int dil[4]     = {1, 2, 4, 8};
    const int skipoff[4] = {184, 80, 8, 0};
    const int Tlen[5]    = {16, 15, 13, 9, 1};

    dim3 adpGrid(32, BB);
    k_TM<<<BB, 512>>>(p1, pk, ind, p2, M1);                              // 0
    k_TM<<<BB, 512>>>(a2p1, a2pk, ind, a2p2, M2);                        // 1
    k_gated0<<<BB * NNODE, 480>>>(inputs, start_w, start_b, S0, G,
        filt_w, filt_b, gate_w, gate_b, skip_w, skip_b, SK, skipoff[0]); // 2
    k_adpE<<<adpGrid, 256>>>(M1, p3, adp);                               // 3 <- profiled
    k_adpE<<<adpGrid, 256>>>(M2, a2p3, adp2);                            // 4

    float* Sbuf[2] = {S0, S1};
    for (int i = 0; i < 3; i++) {
        int Ti = Tlen[i + 1];              // T after layer i
        int L = 32 * Ti;
        dim3 grid((L + 127) / 128, (NNODE + 127) / 128, BB);
        k_gemm_tc<<<grid, 256>>>(adp, G,  Y1, L, L, 0, L, 0);
        k_gemm_tc<<<grid, 256>>>(adp, Y1, Y2, L, L, 0, L, 0);
        k_g01<<<BB * NNODE, 16 * Ti>>>(G, Y1, Y2,
            gconv_w + i * 1536, gconv_b + i * 32, G01, Ti);
        int L2 = 16 * Ti;
        dim3 grid2((L2 + 127) / 128, (NNODE + 127) / 128, BB);
        k_gemm_tc<<<grid2, 256>>>(adp2, G01, Z1, L2, L, L2, L2, 0);
        k_gemm_tc<<<grid2, 256>>>(adp2, Z1,  Z2, L2, L2, 0, L2, 0);
        k_update<<<BB * NNODE, 16 * Ti>>>(Sbuf[i & 1], G01, Z1, Z2,
            ga_w + i * 768, ga_b + i * 16, Sbuf[(i + 1) & 1], dil[i], Tlen[i], Ti);
        int j = i + 1;
        float* Gout = (j < 3) ? G : (float*)nullptr;  // layer-3 G dead
        k_gated<<<BB * NNODE, 16 * Tlen[j + 1]>>>(Sbuf[(i + 1) & 1], Gout,
            filt_w + j * 1024, filt_b + j * 32,
            gate_w + j * 1024, gate_b + j * 32,
            skip_w + j * 128, skip_b + j * 8, SK, skipoff[j],
            dil[j], Tlen[j], Tlen[j + 1]);
    }

    k_end<<<(BB * NNODE + 3) / 4, 128>>>(SK, end1_w, end1_b, end2_w, end2_b, out);
}